// round 12
// baseline (speedup 1.0000x reference)
#include <cuda_runtime.h>
#include <cuda_fp16.h>
#include <cstdint>

using ull = unsigned long long;

#define GG 24
#define II 16
#define OO 16
#define SS 32768            // 32*32*32 spatial
#define NCH 384             // I*G == O*G
#define K2  192             // NCH/2 (fp16 k-pairs)
#define BB 2

// ---------------- device scratch (no allocations allowed) ----------------
__device__ int      g_shift[GG][GG];
__device__ int      g_rot[GG][27];
__device__ uint32_t g_Wh[NCH * K2];          // W^T[n][k-pair] packed f16x2
__device__ uint32_t g_xh[BB * K2 * SS];      // x[b][k-pair][m] packed f16x2 (50 MB)
__device__ float    g_TFB[NCH * 27];         // rotated depthwise taps per (o,z)
__device__ uint32_t g_yh[BB * NCH * (SS/2)]; // y packed f16x2 along m (50 MB)

__device__ __forceinline__ uint32_t smem_u32(const void* p) {
    uint32_t a;
    asm("{ .reg .u64 t; cvta.to.shared.u64 t, %1; cvt.u32.u64 %0, t; }" : "=r"(a) : "l"(p));
    return a;
}
__device__ __forceinline__ void mma_f16(float* c, const uint32_t* a, uint32_t b0, uint32_t b1) {
    asm volatile(
        "mma.sync.aligned.m16n8k16.row.col.f32.f16.f16.f32 "
        "{%0,%1,%2,%3}, {%4,%5,%6,%7}, {%8,%9}, {%0,%1,%2,%3};"
        : "+f"(c[0]), "+f"(c[1]), "+f"(c[2]), "+f"(c[3])
        : "r"(a[0]), "r"(a[1]), "r"(a[2]), "r"(a[3]), "r"(b0), "r"(b1));
}
__device__ __forceinline__ void cpasync16(uint32_t dst, const void* src) {
    asm volatile("cp.async.cg.shared.global [%0], [%1], 16;" :: "r"(dst), "l"(src));
}
#define CP_COMMIT() asm volatile("cp.async.commit_group;" ::: "memory")
#define CP_WAIT(n)  asm volatile("cp.async.wait_group %0;" :: "n"(n) : "memory")

__device__ __forceinline__ uint32_t packh2(float lo, float hi) {
    __half2 h = __halves2half2(__float2half(lo), __float2half(hi));
    return *reinterpret_cast<uint32_t*>(&h);
}
__device__ __forceinline__ float2 h2f2(uint32_t u) {
    return __half22float2(*reinterpret_cast<__half2*>(&u));
}

// ---- packed f32x2 helpers (conv) ----
__device__ __forceinline__ ull ffma2(ull a, ull b, ull c) {
    ull d;
    asm("fma.rn.f32x2 %0, %1, %2, %3;" : "=l"(d) : "l"(a), "l"(b), "l"(c));
    return d;
}
__device__ __forceinline__ ull dup2(float f) {
    ull d;
    asm("mov.b64 %0, {%1, %1};" : "=l"(d) : "f"(f));
    return d;
}
__device__ __forceinline__ ull pk2(float lo, float hi) {
    ull d;
    asm("mov.b64 %0, {%1, %2};" : "=l"(d) : "f"(lo), "f"(hi));
    return d;
}
__device__ __forceinline__ float2 unpack2(ull u) {
    float2 r;
    asm("mov.b64 {%0, %1}, %2;" : "=f"(r.x), "=f"(r.y) : "l"(u));
    return r;
}

// ---------------- table construction (replicates numpy enumeration) -----
__global__ void build_tables_kernel() {
    __shared__ int mats[24][9];
    int tid = threadIdx.x;
    if (tid == 0) {
        const int perms[6][3] = {{0,1,2},{0,2,1},{1,0,2},{1,2,0},{2,0,1},{2,1,0}};
        int cnt = 0;
        for (int p = 0; p < 6; p++)
            for (int sb = 0; sb < 8; sb++) {
                int s0 = (sb & 4) ? -1 : 1, s1 = (sb & 2) ? -1 : 1, s2 = (sb & 1) ? -1 : 1;
                int M[9] = {0,0,0,0,0,0,0,0,0};
                M[0*3 + perms[p][0]] = s0;
                M[1*3 + perms[p][1]] = s1;
                M[2*3 + perms[p][2]] = s2;
                int det = M[0]*(M[4]*M[8]-M[5]*M[7]) - M[1]*(M[3]*M[8]-M[5]*M[6]) + M[2]*(M[3]*M[7]-M[4]*M[6]);
                if (det == 1) { for (int q = 0; q < 9; q++) mats[cnt][q] = M[q]; cnt++; }
            }
    }
    __syncthreads();
    if (tid < 576) {                       // shift[g][h] = idx(Rg^T * Rh)
        int g = tid / 24, h = tid % 24;
        int R[9];
        for (int a = 0; a < 3; a++)
            for (int b = 0; b < 3; b++) {
                int v = 0;
                for (int c = 0; c < 3; c++) v += mats[g][c*3+a] * mats[h][c*3+b];
                R[a*3+b] = v;
            }
        int idx = 0;
        for (int j = 0; j < 24; j++) {
            bool eq = true;
            for (int q = 0; q < 9; q++) if (mats[j][q] != R[q]) { eq = false; break; }
            if (eq) { idx = j; break; }
        }
        g_shift[g][h] = idx;
    }
    if (tid < 648) {                       // rot_idx[g][j]
        int g = tid / 27, j = tid % 27;
        int x0 = j / 9 - 1, x1 = (j / 3) % 3 - 1, x2 = j % 3 - 1;
        int r0 = x0*mats[g][0] + x1*mats[g][3] + x2*mats[g][6] + 1;
        int r1 = x0*mats[g][1] + x1*mats[g][4] + x2*mats[g][7] + 1;
        int r2 = x0*mats[g][2] + x1*mats[g][5] + x2*mats[g][8] + 1;
        g_rot[g][j] = r0*9 + r1*3 + r2;
    }
}

// W^T[n][k2] = pack(W[2k2][n], W[2k2+1][n]) in fp16
__global__ void build_wh_kernel(const float* __restrict__ gw) {
    int idx = blockIdx.x * blockDim.x + threadIdx.x;
    if (idx >= NCH * K2) return;
    int n = idx / K2, k2 = idx % K2;
    int o = n / GG, z = n % GG;
    int k0 = 2 * k2, k1 = 2 * k2 + 1;
    int i0 = k0 / GG, gg0 = k0 % GG;
    int i1 = k1 / GG, gg1 = k1 % GG;
    float w0 = gw[(g_shift[z][gg0] * OO + o) * II + i0];
    float w1 = gw[(g_shift[z][gg1] * OO + o) * II + i1];
    g_Wh[idx] = packh2(w0, w1);
}

__global__ void build_tfb_kernel(const float* __restrict__ tw) {
    int idx = blockIdx.x * blockDim.x + threadIdx.x;
    if (idx >= NCH * 27) return;
    int n = idx / 27, j = idx % 27;
    g_TFB[idx] = tw[(n / GG) * 27 + g_rot[n % GG][j]];
}

// x -> fp16 k-pair packed (one batch per launch)
__global__ void __launch_bounds__(256)
convert_x_kernel(const float* __restrict__ x, int b) {
    int idx = blockIdx.x * blockDim.x + threadIdx.x;   // 0 .. K2*8192-1
    int m4 = (idx & 8191) << 2;
    int k2 = idx >> 13;
    const float* r0 = &x[(((size_t)(b * NCH + 2 * k2)) << 15) + m4];
    float4 a = *(const float4*)r0;
    float4 c = *(const float4*)(r0 + SS);
    uint4 o;
    o.x = packh2(a.x, c.x);
    o.y = packh2(a.y, c.y);
    o.z = packh2(a.z, c.z);
    o.w = packh2(a.w, c.w);
    *(uint4*)&g_xh[(((size_t)(b * K2 + k2)) << 15) + m4] = o;
}

// ================= fp16 mma.sync GEMM, cp.async 4-stage (k16) =================
// CTA 128n x 128m, 24 k-steps of 16; 8 warps (2 n-halves x 4 m-quarters).
// One batch per launch. Proven R9 config.
__global__ void __launch_bounds__(256, 2)
gemm_mma_kernel(const float* __restrict__ gbias, int b) {
    __shared__ uint32_t As[4][128][12];
    __shared__ uint32_t Bs[4][8][136];

    const int tid  = threadIdx.x;
    const int lane = tid & 31;
    const int wid  = tid >> 5;
    const int wr   = wid >> 2;            // 0..1 : n 64-half
    const int wc   = wid & 3;             // 0..3 : m 32-quarter
    const int n0   = blockIdx.x * 128;    // 0,128,256
    const int ms   = blockIdx.y * 128;    // m within batch

    const int gid  = lane >> 2;           // 0..7
    const int tig  = lane & 3;            // 0..3

    float acc[4][4][4];
    #pragma unroll
    for (int i = 0; i < 4; i++)
        #pragma unroll
        for (int j = 0; j < 4; j++)
            #pragma unroll
            for (int q = 0; q < 4; q++) acc[i][j][q] = 0.0f;

    // cp.async slots
    const int arow = tid >> 1, ac = (tid & 1) << 2;      // A: [128 n][8 k2]
    const int brow = tid >> 5, bc = (tid & 31) << 2;     // B: [8 k2][128 m]
    const uint32_t* asrc_base = &g_Wh[(n0 + arow) * K2 + ac];
    const uint32_t* bsrc_base = &g_xh[(((size_t)(b * K2 + brow)) << 15) + ms + bc];

    auto prefetch = [&](int ks, int s) {
        const int k20 = ks * 8;
        cpasync16(smem_u32(&As[s][arow][ac]), asrc_base + k20);
        cpasync16(smem_u32(&Bs[s][brow][bc]), bsrc_base + ((size_t)k20 << 15));
    };

    const int lrow = (lane & 7) + ((lane >> 3) & 1) * 8;
    const int lcol = (lane >> 4) * 4;
    const uint32_t a_base = smem_u32(&As[0][wr * 64 + lrow][lcol]);

    prefetch(0, 0); CP_COMMIT();
    prefetch(1, 1); CP_COMMIT();
    prefetch(2, 2); CP_COMMIT();

    for (int s = 0; s < 24; s++) {
        const int cur = s & 3;
        CP_WAIT(2);
        __syncthreads();
        if (s < 21) prefetch(s + 3, (s + 3) & 3);
        CP_COMMIT();

        uint32_t af[4][4];
        #pragma unroll
        for (int mi = 0; mi < 4; mi++) {
            uint32_t addr = a_base + (uint32_t)(cur * 6144 + mi * 768);
            asm volatile("ldmatrix.sync.aligned.m8n8.x4.shared.b16 {%0,%1,%2,%3}, [%4];"
                         : "=r"(af[mi][0]), "=r"(af[mi][1]), "=r"(af[mi][2]), "=r"(af[mi][3])
                         : "r"(addr));
        }
        uint32_t bf[4][2];
        #pragma unroll
        for (int ni = 0; ni < 4; ni++) {
            int m = wc * 32 + ni * 8 + gid;
            bf[ni][0] = Bs[cur][tig][m];
            bf[ni][1] = Bs[cur][tig + 4][m];
        }
        #pragma unroll
        for (int mi = 0; mi < 4; mi++)
            #pragma unroll
            for (int ni = 0; ni < 4; ni++)
                mma_f16(acc[mi][ni], af[mi], bf[ni][0], bf[ni][1]);
    }

    // epilogue: add bias, pack fp16 m-pairs, store u32
    #pragma unroll
    for (int mi = 0; mi < 4; mi++) {
        int nlo = n0 + wr * 64 + mi * 16 + gid;
        float blo = gbias[nlo / GG];
        float bhi = gbias[(nlo + 8) / GG];
        uint32_t* rowlo = &g_yh[(((size_t)(b * NCH + nlo)) << 14) + (ms >> 1)];
        uint32_t* rowhi = rowlo + ((size_t)8 << 14);
        #pragma unroll
        for (int ni = 0; ni < 4; ni++) {
            int m = wc * 32 + ni * 8 + tig * 2;
            rowlo[m >> 1] = packh2(acc[mi][ni][0] + blo, acc[mi][ni][1] + blo);
            rowhi[m >> 1] = packh2(acc[mi][ni][2] + bhi, acc[mi][ni][3] + bhi);
        }
    }
}

// ================= depthwise 3x3x3 conv + bias + leaky ReLU (f32x2) =========
// One batch per launch; grid 1536 = 384 channels x 4 h-slabs.
__global__ void __launch_bounds__(256)
conv_kernel(float* __restrict__ out, const float* __restrict__ tbias, int b) {
    __shared__ float tile[10][34][34];
    __shared__ float2 tap2[27];
    __shared__ float sbias;

    const int chl = blockIdx.x >> 2;           // 0..383
    const int ch  = b * NCH + chl;
    const int h0 = (blockIdx.x & 3) * 8;
    const int tid = threadIdx.x;

    const uint32_t* ybase = g_yh + ((size_t)ch << 14);
    if (tid < 27) {
        float t = g_TFB[chl * 27 + tid];
        tap2[tid] = make_float2(t, t);
    }
    if (tid == 27) sbias = tbias[0];

    {
        float4* tz = (float4*)&tile[0][0][0];
        for (int i = tid; i < 2890; i += 256) tz[i] = make_float4(0.f, 0.f, 0.f, 0.f);
    }
    __syncthreads();

    {
        const int ww = tid >> 3;
        const int dd0 = (tid & 7) << 2;
        #pragma unroll
        for (int hh = 0; hh < 10; hh++) {
            int gh = h0 + hh - 1;
            if (gh >= 0 && gh < 32) {
                uint2 v = *(const uint2*)&ybase[(gh * 32 + ww) * 16 + (dd0 >> 1)];
                float2 p0 = h2f2(v.x);
                float2 p1 = h2f2(v.y);
                float* trow = &tile[hh][ww + 1][1 + dd0];
                trow[0] = p0.x; trow[1] = p0.y; trow[2] = p1.x; trow[3] = p1.y;
            }
        }
    }
    __syncthreads();

    float* obase = out + (size_t)ch * SS + (size_t)h0 * 1024;
    #pragma unroll 1
    for (int it = 0; it < 2; it++) {
        int q = tid + it * 256;            // 0..511
        int d0 = (q & 3) << 3;             // 0,8,16,24
        int w = (q >> 2) & 31;
        int h = (q >> 7) * 2;              // 0,2,4,6
        ull aA[4], aB[4];
        #pragma unroll
        for (int i = 0; i < 4; i++) { aA[i] = dup2(sbias); aB[i] = dup2(sbias); }

        #pragma unroll
        for (int ar = 0; ar < 4; ar++)
            #pragma unroll
            for (int bq = 0; bq < 3; bq++) {
                const float* rp = &tile[h + ar][w + bq][d0];
                float2 f0 = *(const float2*)(rp + 0);
                float2 f1 = *(const float2*)(rp + 2);
                float2 f2 = *(const float2*)(rp + 4);
                float2 f3 = *(const float2*)(rp + 6);
                float2 f4 = *(const float2*)(rp + 8);
                ull w0 = pk2(f0.x, f0.y), w1 = pk2(f1.x, f1.y), w2 = pk2(f2.x, f2.y);
                ull w3 = pk2(f3.x, f3.y), w4 = pk2(f4.x, f4.y);
                ull s0 = pk2(f0.y, f1.x), s1 = pk2(f1.y, f2.x);
                ull s2 = pk2(f2.y, f3.x), s3 = pk2(f3.y, f4.x);
                if (ar < 3) {
                    const ull* tp = (const ull*)&tap2[ar * 9 + bq * 3];
                    ull t0 = tp[0], t1 = tp[1], t2 = tp[2];
                    aA[0] = ffma2(t0, w0, aA[0]); aA[0] = ffma2(t1, s0, aA[0]); aA[0] = ffma2(t2, w1, aA[0]);
                    aA[1] = ffma2(t0, w1, aA[1]); aA[1] = ffma2(t1, s1, aA[1]); aA[1] = ffma2(t2, w2, aA[1]);
                    aA[2] = ffma2(t0, w2, aA[2]); aA[2] = ffma2(t1, s2, aA[2]); aA[2] = ffma2(t2, w3, aA[2]);
                    aA[3] = ffma2(t0, w3, aA[3]); aA[3] = ffma2(t1, s3, aA[3]); aA[3] = ffma2(t2, w4, aA[3]);
                }
                if (ar > 0) {
                    const ull* tp = (const ull*)&tap2[(ar - 1) * 9 + bq * 3];
                    ull t0 = tp[0], t1 = tp[1], t2 = tp[2];
                    aB[0] = ffma2(t0, w0, aB[0]); aB[0] = ffma2(t1, s0, aB[0]); aB[0] = ffma2(t2, w1, aB[0]);
                    aB[1] = ffma2(t0, w1, aB[1]); aB[1] = ffma2(t1, s1, aB[1]); aB[1] = ffma2(t2, w2, aB[1]);
                    aB[2] = ffma2(t0, w2, aB[2]); aB[2] = ffma2(t1, s2, aB[2]); aB[2] = ffma2(t2, w3, aB[2]);
                    aB[3] = ffma2(t0, w3, aB[3]); aB[3] = ffma2(t1, s3, aB[3]); aB[3] = ffma2(t2, w4, aB[3]);
                }
            }

        #pragma unroll
        for (int hh = 0; hh < 2; hh++) {
            const ull* A = hh ? aB : aA;
            float2 u0 = unpack2(A[0]), u1 = unpack2(A[1]), u2 = unpack2(A[2]), u3 = unpack2(A[3]);
            float4 o0, o1;
            o0.x = u0.x > 0.0f ? u0.x : 0.01f * u0.x;
            o0.y = u0.y > 0.0f ? u0.y : 0.01f * u0.y;
            o0.z = u1.x > 0.0f ? u1.x : 0.01f * u1.x;
            o0.w = u1.y > 0.0f ? u1.y : 0.01f * u1.y;
            o1.x = u2.x > 0.0f ? u2.x : 0.01f * u2.x;
            o1.y = u2.y > 0.0f ? u2.y : 0.01f * u2.y;
            o1.z = u3.x > 0.0f ? u3.x : 0.01f * u3.x;
            o1.w = u3.y > 0.0f ? u3.y : 0.01f * u3.y;
            float* dst = obase + (((h + hh) * 32 + w) * 32 + d0);
            *(float4*)dst = o0;
            *(float4*)(dst + 4) = o1;
        }
    }
}

// ---------------- launch: 2-batch pipeline with forked capture stream -------
extern "C" void kernel_launch(void* const* d_in, const int* in_sizes, int n_in,
                              void* d_out, int out_size) {
    const float* x  = (const float*)d_in[0];
    const float* gw = (const float*)d_in[1];
    const float* tw = (const float*)d_in[2];
    const float* gb = (const float*)d_in[3];
    const float* tb = (const float*)d_in[4];
    float* out = (float*)d_out;

    cudaStream_t s2;
    cudaStreamCreateWithFlags(&s2, cudaStreamNonBlocking);
    cudaEvent_t evFork, evBuild, evC1, evG0, evJoin;
    cudaEventCreateWithFlags(&evFork,  cudaEventDisableTiming);
    cudaEventCreateWithFlags(&evBuild, cudaEventDisableTiming);
    cudaEventCreateWithFlags(&evC1,    cudaEventDisableTiming);
    cudaEventCreateWithFlags(&evG0,    cudaEventDisableTiming);
    cudaEventCreateWithFlags(&evJoin,  cudaEventDisableTiming);

    // fork s2 off the (capturing) default stream
    cudaEventRecord(evFork, 0);
    cudaStreamWaitEvent(s2, evFork, 0);

    // s2: table/filter builds, then convert batch 1
    build_tables_kernel<<<1, 648, 0, s2>>>();
    build_wh_kernel<<<(NCH * K2 + 255) / 256, 256, 0, s2>>>(gw);
    build_tfb_kernel<<<(NCH * 27 + 255) / 256, 256, 0, s2>>>(tw);
    cudaEventRecord(evBuild, s2);
    convert_x_kernel<<<K2 * 8192 / 256, 256, 0, s2>>>(x, 1);
    cudaEventRecord(evC1, s2);

    // main: convert batch 0, then gemm0 (needs builds)
    convert_x_kernel<<<K2 * 8192 / 256, 256>>>(x, 0);
    cudaStreamWaitEvent(0, evBuild, 0);
    dim3 gg(3, 256);
    gemm_mma_kernel<<<gg, 256>>>(gb, 0);
    cudaEventRecord(evG0, 0);

    // main: gemm1 (needs convert1);  s2: conv0 (needs gemm0) — these overlap
    cudaStreamWaitEvent(0, evC1, 0);
    gemm_mma_kernel<<<gg, 256>>>(gb, 1);
    cudaStreamWaitEvent(s2, evG0, 0);
    conv_kernel<<<1536, 256, 0, s2>>>(out, tb, 0);
    cudaEventRecord(evJoin, s2);

    // join: conv1 on main after gemm1 and conv0's branch
    cudaStreamWaitEvent(0, evJoin, 0);
    conv_kernel<<<1536, 256>>>(out, tb, 1);
    // (streams/events intentionally not destroyed: kernel_launch is called
    //  only twice — correctness + capture — and destruction of a forked
    //  stream during active capture is illegal)
}

// round 14
// speedup vs baseline: 1.1292x; 1.1292x over previous
#include <cuda_runtime.h>
#include <cuda_fp16.h>
#include <cstdint>

using ull = unsigned long long;

#define GG 24
#define II 16
#define OO 16
#define SS 32768            // 32*32*32 spatial
#define NCH 384             // I*G == O*G
#define K2  192             // NCH/2 (fp16 k-pairs)
#define BB 2

#define NSTAGE 6
#define AS_STRIDE 1536      // u32 per A stage (128*12)
#define BS_STRIDE 1088      // u32 per B stage (8*136)
#define SMEM_BYTES (NSTAGE * (AS_STRIDE + BS_STRIDE) * 4)   // 62976

// ---------------- device scratch (no allocations allowed) ----------------
__device__ int      g_shift[GG][GG];
__device__ int      g_rot[GG][27];
__device__ uint32_t g_Wh[NCH * K2];          // W^T[n][k-pair] packed f16x2
__device__ uint32_t g_xh[BB * K2 * SS];      // x[b][k-pair][m] packed f16x2 (50 MB)
__device__ float    g_TFB[NCH * 27];         // rotated depthwise taps per (o,z)
__device__ uint32_t g_yh[BB * NCH * (SS/2)]; // y packed f16x2 along m (50 MB)

__device__ __forceinline__ uint32_t smem_u32(const void* p) {
    uint32_t a;
    asm("{ .reg .u64 t; cvta.to.shared.u64 t, %1; cvt.u32.u64 %0, t; }" : "=r"(a) : "l"(p));
    return a;
}
__device__ __forceinline__ void mma_f16(float* c, const uint32_t* a, uint32_t b0, uint32_t b1) {
    asm volatile(
        "mma.sync.aligned.m16n8k16.row.col.f32.f16.f16.f32 "
        "{%0,%1,%2,%3}, {%4,%5,%6,%7}, {%8,%9}, {%0,%1,%2,%3};"
        : "+f"(c[0]), "+f"(c[1]), "+f"(c[2]), "+f"(c[3])
        : "r"(a[0]), "r"(a[1]), "r"(a[2]), "r"(a[3]), "r"(b0), "r"(b1));
}
__device__ __forceinline__ void cpasync16(uint32_t dst, const void* src) {
    asm volatile("cp.async.cg.shared.global [%0], [%1], 16;" :: "r"(dst), "l"(src));
}
#define CP_COMMIT() asm volatile("cp.async.commit_group;" ::: "memory")
#define CP_WAIT(n)  asm volatile("cp.async.wait_group %0;" :: "n"(n) : "memory")

__device__ __forceinline__ uint32_t packh2(float lo, float hi) {
    __half2 h = __halves2half2(__float2half(lo), __float2half(hi));
    return *reinterpret_cast<uint32_t*>(&h);
}
__device__ __forceinline__ float2 h2f2(uint32_t u) {
    return __half22float2(*reinterpret_cast<__half2*>(&u));
}

// ---- packed f32x2 helpers (conv) ----
__device__ __forceinline__ ull ffma2(ull a, ull b, ull c) {
    ull d;
    asm("fma.rn.f32x2 %0, %1, %2, %3;" : "=l"(d) : "l"(a), "l"(b), "l"(c));
    return d;
}
__device__ __forceinline__ ull dup2(float f) {
    ull d;
    asm("mov.b64 %0, {%1, %1};" : "=l"(d) : "f"(f));
    return d;
}
__device__ __forceinline__ ull pk2(float lo, float hi) {
    ull d;
    asm("mov.b64 %0, {%1, %2};" : "=l"(d) : "f"(lo), "f"(hi));
    return d;
}
__device__ __forceinline__ float2 unpack2(ull u) {
    float2 r;
    asm("mov.b64 {%0, %1}, %2;" : "=f"(r.x), "=f"(r.y) : "l"(u));
    return r;
}

// ---------------- table construction (replicates numpy enumeration) -----
__global__ void build_tables_kernel() {
    __shared__ int mats[24][9];
    int tid = threadIdx.x;
    if (tid == 0) {
        const int perms[6][3] = {{0,1,2},{0,2,1},{1,0,2},{1,2,0},{2,0,1},{2,1,0}};
        int cnt = 0;
        for (int p = 0; p < 6; p++)
            for (int sb = 0; sb < 8; sb++) {
                int s0 = (sb & 4) ? -1 : 1, s1 = (sb & 2) ? -1 : 1, s2 = (sb & 1) ? -1 : 1;
                int M[9] = {0,0,0,0,0,0,0,0,0};
                M[0*3 + perms[p][0]] = s0;
                M[1*3 + perms[p][1]] = s1;
                M[2*3 + perms[p][2]] = s2;
                int det = M[0]*(M[4]*M[8]-M[5]*M[7]) - M[1]*(M[3]*M[8]-M[5]*M[6]) + M[2]*(M[3]*M[7]-M[4]*M[6]);
                if (det == 1) { for (int q = 0; q < 9; q++) mats[cnt][q] = M[q]; cnt++; }
            }
    }
    __syncthreads();
    if (tid < 576) {                       // shift[g][h] = idx(Rg^T * Rh)
        int g = tid / 24, h = tid % 24;
        int R[9];
        for (int a = 0; a < 3; a++)
            for (int b = 0; b < 3; b++) {
                int v = 0;
                for (int c = 0; c < 3; c++) v += mats[g][c*3+a] * mats[h][c*3+b];
                R[a*3+b] = v;
            }
        int idx = 0;
        for (int j = 0; j < 24; j++) {
            bool eq = true;
            for (int q = 0; q < 9; q++) if (mats[j][q] != R[q]) { eq = false; break; }
            if (eq) { idx = j; break; }
        }
        g_shift[g][h] = idx;
    }
    if (tid < 648) {                       // rot_idx[g][j]
        int g = tid / 27, j = tid % 27;
        int x0 = j / 9 - 1, x1 = (j / 3) % 3 - 1, x2 = j % 3 - 1;
        int r0 = x0*mats[g][0] + x1*mats[g][3] + x2*mats[g][6] + 1;
        int r1 = x0*mats[g][1] + x1*mats[g][4] + x2*mats[g][7] + 1;
        int r2 = x0*mats[g][2] + x1*mats[g][5] + x2*mats[g][8] + 1;
        g_rot[g][j] = r0*9 + r1*3 + r2;
    }
}

// W^T[n][k2] = pack(W[2k2][n], W[2k2+1][n]) in fp16
__global__ void build_wh_kernel(const float* __restrict__ gw) {
    int idx = blockIdx.x * blockDim.x + threadIdx.x;
    if (idx >= NCH * K2) return;
    int n = idx / K2, k2 = idx % K2;
    int o = n / GG, z = n % GG;
    int k0 = 2 * k2, k1 = 2 * k2 + 1;
    int i0 = k0 / GG, gg0 = k0 % GG;
    int i1 = k1 / GG, gg1 = k1 % GG;
    float w0 = gw[(g_shift[z][gg0] * OO + o) * II + i0];
    float w1 = gw[(g_shift[z][gg1] * OO + o) * II + i1];
    g_Wh[idx] = packh2(w0, w1);
}

__global__ void build_tfb_kernel(const float* __restrict__ tw) {
    int idx = blockIdx.x * blockDim.x + threadIdx.x;
    if (idx >= NCH * 27) return;
    int n = idx / 27, j = idx % 27;
    g_TFB[idx] = tw[(n / GG) * 27 + g_rot[n % GG][j]];
}

// x -> fp16 k-pair packed
__global__ void __launch_bounds__(256)
convert_x_kernel(const float* __restrict__ x) {
    int idx = blockIdx.x * blockDim.x + threadIdx.x;   // 0 .. BB*K2*8192-1
    int m4 = (idx & 8191) << 2;
    int k2 = (idx >> 13) % K2;
    int b  = idx / (K2 * 8192);
    const float* r0 = &x[(((size_t)(b * NCH + 2 * k2)) << 15) + m4];
    float4 a = *(const float4*)r0;
    float4 c = *(const float4*)(r0 + SS);
    uint4 o;
    o.x = packh2(a.x, c.x);
    o.y = packh2(a.y, c.y);
    o.z = packh2(a.z, c.z);
    o.w = packh2(a.w, c.w);
    *(uint4*)&g_xh[(((size_t)(b * K2 + k2)) << 15) + m4] = o;
}

// ================= fp16 mma.sync GEMM, cp.async 6-stage (k16) =================
// CTA 128n x 128m, 24 k-steps of 16; 8 warps (2 n-halves x 4 m-quarters).
// 6 smem stages, prefetch distance 4, CP_WAIT(3), barrier EVERY step (safe
// cross-thread visibility protocol; R13's alternate-barrier scheme raced).
__global__ void __launch_bounds__(256, 2)
gemm_mma_kernel(const float* __restrict__ gbias) {
    extern __shared__ uint32_t dynsmem[];
    uint32_t* AsB = dynsmem;                         // [6][128][12]
    uint32_t* BsB = dynsmem + NSTAGE * AS_STRIDE;    // [6][8][136]

    const int tid  = threadIdx.x;
    const int lane = tid & 31;
    const int wid  = tid >> 5;
    const int wr   = wid >> 2;            // 0..1 : n 64-half
    const int wc   = wid & 3;             // 0..3 : m 32-quarter
    const int n0   = blockIdx.x * 128;    // 0,128,256
    const int m0   = blockIdx.y * 128;
    const int b    = m0 >> 15;
    const int ms   = m0 & (SS - 1);

    const int gid  = lane >> 2;           // 0..7
    const int tig  = lane & 3;            // 0..3

    float acc[4][4][4];
    #pragma unroll
    for (int i = 0; i < 4; i++)
        #pragma unroll
        for (int j = 0; j < 4; j++)
            #pragma unroll
            for (int q = 0; q < 4; q++) acc[i][j][q] = 0.0f;

    // cp.async slots
    const int arow = tid >> 1, ac = (tid & 1) << 2;      // A: [128 n][8 k2]
    const int brow = tid >> 5, bc = (tid & 31) << 2;     // B: [8 k2][128 m]
    const uint32_t* asrc_base = &g_Wh[(n0 + arow) * K2 + ac];
    const uint32_t* bsrc_base = &g_xh[(((size_t)(b * K2 + brow)) << 15) + ms + bc];
    const uint32_t a_sts = smem_u32(AsB + arow * 12 + ac);
    const uint32_t b_sts = smem_u32(BsB + brow * 136 + bc);

    auto prefetch = [&](int ks, int s) {
        const int k20 = ks * 8;
        cpasync16(a_sts + (uint32_t)(s * AS_STRIDE * 4), asrc_base + k20);
        cpasync16(b_sts + (uint32_t)(s * BS_STRIDE * 4), bsrc_base + ((size_t)k20 << 15));
    };

    // ldmatrix lane base (pitch-12 conflict-free)
    const int lrow = (lane & 7) + ((lane >> 3) & 1) * 8;
    const int lcol = (lane >> 4) * 4;
    const uint32_t a_base = smem_u32(AsB + (wr * 64 + lrow) * 12 + lcol);
    const uint32_t* BsW = BsB + wc * 32;

    prefetch(0, 0); CP_COMMIT();
    prefetch(1, 1); CP_COMMIT();
    prefetch(2, 2); CP_COMMIT();
    prefetch(3, 3); CP_COMMIT();

    for (int s = 0; s < 24; s++) {
        const int cur = s % NSTAGE;
        CP_WAIT(3);                  // groups <= s complete (4 in flight after init)
        __syncthreads();             // all warps confirmed buffer cur
        if (s < 20) prefetch(s + 4, (s + 4) % NSTAGE);   // overwrites buffer (s-2)%6
        CP_COMMIT();

        uint32_t af[4][4];
        #pragma unroll
        for (int mi = 0; mi < 4; mi++) {
            uint32_t addr = a_base + (uint32_t)(cur * (AS_STRIDE * 4) + mi * 768);
            asm volatile("ldmatrix.sync.aligned.m8n8.x4.shared.b16 {%0,%1,%2,%3}, [%4];"
                         : "=r"(af[mi][0]), "=r"(af[mi][1]), "=r"(af[mi][2]), "=r"(af[mi][3])
                         : "r"(addr));
        }
        const uint32_t* Bsr = BsW + cur * BS_STRIDE;
        uint32_t bf[4][2];
        #pragma unroll
        for (int ni = 0; ni < 4; ni++) {
            int m = ni * 8 + gid;
            bf[ni][0] = Bsr[tig * 136 + m];
            bf[ni][1] = Bsr[(tig + 4) * 136 + m];
        }
        #pragma unroll
        for (int mi = 0; mi < 4; mi++)
            #pragma unroll
            for (int ni = 0; ni < 4; ni++)
                mma_f16(acc[mi][ni], af[mi], bf[ni][0], bf[ni][1]);
    }

    // epilogue: add bias, pack fp16 m-pairs, store u32
    #pragma unroll
    for (int mi = 0; mi < 4; mi++) {
        int nlo = n0 + wr * 64 + mi * 16 + gid;
        float blo = gbias[nlo / GG];
        float bhi = gbias[(nlo + 8) / GG];
        uint32_t* rowlo = &g_yh[(((size_t)(b * NCH + nlo)) << 14) + (ms >> 1)];
        uint32_t* rowhi = rowlo + ((size_t)8 << 14);
        #pragma unroll
        for (int ni = 0; ni < 4; ni++) {
            int m = wc * 32 + ni * 8 + tig * 2;
            rowlo[m >> 1] = packh2(acc[mi][ni][0] + blo, acc[mi][ni][1] + blo);
            rowhi[m >> 1] = packh2(acc[mi][ni][2] + bhi, acc[mi][ni][3] + bhi);
        }
    }
}

// ================= depthwise 3x3x3 conv + bias + leaky ReLU (f32x2) =========
__global__ void __launch_bounds__(256)
conv_kernel(float* __restrict__ out, const float* __restrict__ tbias) {
    __shared__ float tile[10][34][34];
    __shared__ float2 tap2[27];
    __shared__ float sbias;

    const int ch = blockIdx.x >> 2;
    const int h0 = (blockIdx.x & 3) * 8;
    const int tid = threadIdx.x;

    const uint32_t* ybase = g_yh + ((size_t)ch << 14);
    if (tid < 27) {
        float t = g_TFB[(ch % NCH) * 27 + tid];
        tap2[tid] = make_float2(t, t);
    }
    if (tid == 27) sbias = tbias[0];

    {
        float4* tz = (float4*)&tile[0][0][0];
        for (int i = tid; i < 2890; i += 256) tz[i] = make_float4(0.f, 0.f, 0.f, 0.f);
    }
    __syncthreads();

    {
        const int ww = tid >> 3;
        const int dd0 = (tid & 7) << 2;
        #pragma unroll
        for (int hh = 0; hh < 10; hh++) {
            int gh = h0 + hh - 1;
            if (gh >= 0 && gh < 32) {
                uint2 v = *(const uint2*)&ybase[(gh * 32 + ww) * 16 + (dd0 >> 1)];
                float2 p0 = h2f2(v.x);
                float2 p1 = h2f2(v.y);
                float* trow = &tile[hh][ww + 1][1 + dd0];
                trow[0] = p0.x; trow[1] = p0.y; trow[2] = p1.x; trow[3] = p1.y;
            }
        }
    }
    __syncthreads();

    float* obase = out + (size_t)ch * SS + (size_t)h0 * 1024;
    #pragma unroll 1
    for (int it = 0; it < 2; it++) {
        int q = tid + it * 256;            // 0..511
        int d0 = (q & 3) << 3;             // 0,8,16,24
        int w = (q >> 2) & 31;
        int h = (q >> 7) * 2;              // 0,2,4,6
        ull aA[4], aB[4];
        #pragma unroll
        for (int i = 0; i < 4; i++) { aA[i] = dup2(sbias); aB[i] = dup2(sbias); }

        #pragma unroll
        for (int ar = 0; ar < 4; ar++)
            #pragma unroll
            for (int bq = 0; bq < 3; bq++) {
                const float* rp = &tile[h + ar][w + bq][d0];
                float2 f0 = *(const float2*)(rp + 0);
                float2 f1 = *(const float2*)(rp + 2);
                float2 f2 = *(const float2*)(rp + 4);
                float2 f3 = *(const float2*)(rp + 6);
                float2 f4 = *(const float2*)(rp + 8);
                ull w0 = pk2(f0.x, f0.y), w1 = pk2(f1.x, f1.y), w2 = pk2(f2.x, f2.y);
                ull w3 = pk2(f3.x, f3.y), w4 = pk2(f4.x, f4.y);
                ull s0 = pk2(f0.y, f1.x), s1 = pk2(f1.y, f2.x);
                ull s2 = pk2(f2.y, f3.x), s3 = pk2(f3.y, f4.x);
                if (ar < 3) {
                    const ull* tp = (const ull*)&tap2[ar * 9 + bq * 3];
                    ull t0 = tp[0], t1 = tp[1], t2 = tp[2];
                    aA[0] = ffma2(t0, w0, aA[0]); aA[0] = ffma2(t1, s0, aA[0]); aA[0] = ffma2(t2, w1, aA[0]);
                    aA[1] = ffma2(t0, w1, aA[1]); aA[1] = ffma2(t1, s1, aA[1]); aA[1] = ffma2(t2, w2, aA[1]);
                    aA[2] = ffma2(t0, w2, aA[2]); aA[2] = ffma2(t1, s2, aA[2]); aA[2] = ffma2(t2, w3, aA[2]);
                    aA[3] = ffma2(t0, w3, aA[3]); aA[3] = ffma2(t1, s3, aA[3]); aA[3] = ffma2(t2, w4, aA[3]);
                }
                if (ar > 0) {
                    const ull* tp = (const ull*)&tap2[(ar - 1) * 9 + bq * 3];
                    ull t0 = tp[0], t1 = tp[1], t2 = tp[2];
                    aB[0] = ffma2(t0, w0, aB[0]); aB[0] = ffma2(t1, s0, aB[0]); aB[0] = ffma2(t2, w1, aB[0]);
                    aB[1] = ffma2(t0, w1, aB[1]); aB[1] = ffma2(t1, s1, aB[1]); aB[1] = ffma2(t2, w2, aB[1]);
                    aB[2] = ffma2(t0, w2, aB[2]); aB[2] = ffma2(t1, s2, aB[2]); aB[2] = ffma2(t2, w3, aB[2]);
                    aB[3] = ffma2(t0, w3, aB[3]); aB[3] = ffma2(t1, s3, aB[3]); aB[3] = ffma2(t2, w4, aB[3]);
                }
            }

        #pragma unroll
        for (int hh = 0; hh < 2; hh++) {
            const ull* A = hh ? aB : aA;
            float2 u0 = unpack2(A[0]), u1 = unpack2(A[1]), u2 = unpack2(A[2]), u3 = unpack2(A[3]);
            float4 o0, o1;
            o0.x = u0.x > 0.0f ? u0.x : 0.01f * u0.x;
            o0.y = u0.y > 0.0f ? u0.y : 0.01f * u0.y;
            o0.z = u1.x > 0.0f ? u1.x : 0.01f * u1.x;
            o0.w = u1.y > 0.0f ? u1.y : 0.01f * u1.y;
            o1.x = u2.x > 0.0f ? u2.x : 0.01f * u2.x;
            o1.y = u2.y > 0.0f ? u2.y : 0.01f * u2.y;
            o1.z = u3.x > 0.0f ? u3.x : 0.01f * u3.x;
            o1.w = u3.y > 0.0f ? u3.y : 0.01f * u3.y;
            float* dst = obase + (((h + hh) * 32 + w) * 32 + d0);
            *(float4*)dst = o0;
            *(float4*)(dst + 4) = o1;
        }
    }
}

// ---------------- launch ----------------
extern "C" void kernel_launch(void* const* d_in, const int* in_sizes, int n_in,
                              void* d_out, int out_size) {
    const float* x  = (const float*)d_in[0];
    const float* gw = (const float*)d_in[1];
    const float* tw = (const float*)d_in[2];
    const float* gb = (const float*)d_in[3];
    const float* tb = (const float*)d_in[4];
    float* out = (float*)d_out;

    cudaFuncSetAttribute(gemm_mma_kernel,
                         cudaFuncAttributeMaxDynamicSharedMemorySize, SMEM_BYTES);

    build_tables_kernel<<<1, 648>>>();
    build_wh_kernel<<<(NCH * K2 + 255) / 256, 256>>>(gw);
    build_tfb_kernel<<<(NCH * 27 + 255) / 256, 256>>>(tw);
    convert_x_kernel<<<BB * K2 * 8192 / 256, 256>>>(x);

    dim3 gg(3, 512);      // x = n-tile fastest: CTAs sharing an m-stripe co-scheduled
    gemm_mma_kernel<<<gg, 256, SMEM_BYTES>>>(gb);
    conv_kernel<<<3072, 256>>>(out, tb);
}